// round 13
// baseline (speedup 1.0000x reference)
#include <cuda_runtime.h>
#include <cuda_bf16.h>

#define BLK 256
#define WPC 8
#define CTAS_PER_SM 6
#define GRID_CTAS (148 * CTAS_PER_SM)   /* 888 */
#define MAX_PARTIALS 8192

#define LOG2E 1.44269504088896340736f
#define LN2   0.69314718055994530942f

__device__ float g_partials[MAX_PARTIALS];
__device__ int   g_done = 0;

__device__ __forceinline__ float ex2f(float x) {
    float r; asm("ex2.approx.ftz.f32 %0, %1;" : "=f"(r) : "f"(x)); return r;
}
__device__ __forceinline__ float lg2f(float x) {
    float r; asm("lg2.approx.ftz.f32 %0, %1;" : "=f"(r) : "f"(x)); return r;
}

__inline__ __device__ float warp_sum(float v) {
    #pragma unroll
    for (int o = 16; o > 0; o >>= 1)
        v += __shfl_xor_sync(0xFFFFFFFFu, v, o);
    return v;
}

// accumulate one float4: e = exp(v) = 2^(v*log2e), l = log2(1 + e*K)
__device__ __forceinline__ void acc4(const float4 q, const float K,
                                     float& se, float& sl)
{
    const float e0 = ex2f(q.x * LOG2E);
    const float e1 = ex2f(q.y * LOG2E);
    const float e2 = ex2f(q.z * LOG2E);
    const float e3 = ex2f(q.w * LOG2E);
    const float l0 = lg2f(fmaf(e0, K, 1.0f));
    const float l1 = lg2f(fmaf(e1, K, 1.0f));
    const float l2 = lg2f(fmaf(e2, K, 1.0f));
    const float l3 = lg2f(fmaf(e3, K, 1.0f));
    se += (e0 + e1) + (e2 + e3);
    sl = fmaf(e0, l0, sl);
    sl = fmaf(e1, l1, sl);
    sl = fmaf(e2, l2, sl);
    sl = fmaf(e3, l3, sl);
}

__device__ __forceinline__ void acc1(const float v, const float K,
                                     float& se, float& sl)
{
    const float e = ex2f(v * LOG2E);
    const float l = lg2f(fmaf(e, K, 1.0f));
    se += e;
    sl = fmaf(e, l, sl);
}

// Persistent kernel, one row per warp, cross-row software pipelining:
// next row's K-chain + first two float4 loads issue BEFORE the current
// row's warp reduction, hiding reduction + load latency.
__global__ __launch_bounds__(BLK, CTAS_PER_SM) void loss_kernel(
    const float* __restrict__ in, int C, int B, float* __restrict__ out)
{
    const int t    = threadIdx.x;
    const int lane = t & 31;
    const int wid  = t >> 5;
    const int warp_gid = blockIdx.x * WPC + wid;
    const int nwarps   = gridDim.x * WPC;

    __shared__ float sh_row[WPC];

    float rowacc = 0.0f;

    if (C == 1000) {
        // ---- specialized fast path: row stride 1001, nfull == 7 always ----
        int row = warp_gid;
        bool valid = row < B;

        size_t S = 0, A = 0;
        int head = 0, n4 = 0, tail = 0;
        const float4* fp4 = nullptr;
        float Kn = 0.0f;
        float4 p0, p1;

        if (valid) {
            S = (size_t)row * 1001u;
            A = (S + 3) & ~(size_t)3;
            head = (int)(A - S);
            const int body = 1000 - head;
            n4 = body >> 2;
            tail = body & 3;
            fp4 = (const float4*)(in + A);
            Kn = ex2f(-__ldg(in + S + 1000) * LOG2E);
            p0 = __ldg(fp4 + lane);
            p1 = __ldg(fp4 + 32 + lane);
        }

        while (valid) {
            const float K = Kn;
            const float4 q0 = p0, q1 = p1;
            const float4* f4 = fp4;
            const size_t Sc = S;
            const int headc = head, n4c = n4, tailc = tail;

            // rest of current row's front loads
            const float4 q2 = __ldg(f4 + 64 + lane);
            const float4 q3 = __ldg(f4 + 96 + lane);
            const bool has_r = (224 + lane) < n4c;
            const bool has_h = lane < headc;
            const bool has_t = lane < tailc;
            float4 qr; if (has_r) qr = __ldg(f4 + 224 + lane);
            float vh = 0.0f, vt = 0.0f;
            if (has_h) vh = __ldg(in + Sc + lane);
            if (has_t) vt = __ldg(in + Sc + 1000 - tailc + lane);

            float se = 0.0f, sl = 0.0f;

            acc4(q0, K, se, sl);
            const float4 q4 = __ldg(f4 + 128 + lane);
            acc4(q1, K, se, sl);
            const float4 q5 = __ldg(f4 + 160 + lane);
            acc4(q2, K, se, sl);
            const float4 q6 = __ldg(f4 + 192 + lane);
            acc4(q3, K, se, sl);

            // ---- prefetch next row while MUFU chains drain ----
            const int nrow = row + nwarps;
            valid = nrow < B;
            if (valid) {
                S = (size_t)nrow * 1001u;
                A = (S + 3) & ~(size_t)3;
                head = (int)(A - S);
                const int body = 1000 - head;
                n4 = body >> 2;
                tail = body & 3;
                fp4 = (const float4*)(in + A);
                Kn = ex2f(-__ldg(in + S + 1000) * LOG2E);
                p0 = __ldg(fp4 + lane);
                p1 = __ldg(fp4 + 32 + lane);
            }

            acc4(q4, K, se, sl);
            acc4(q5, K, se, sl);
            acc4(q6, K, se, sl);
            if (has_r) acc4(qr, K, se, sl);
            if (has_h) acc1(vh, K, se, sl);
            if (has_t) acc1(vt, K, se, sl);

            // reduction overlaps the prefetched next-row loads
            se = warp_sum(se);
            sl = warp_sum(sl);
            rowacc += __fdividef(sl, se);

            row = nrow;
        }
    } else {
        // ---- generic fallback (any C) ----
        for (int row = warp_gid; row < B; row += nwarps) {
            const size_t S = (size_t)row * (size_t)(C + 1);
            const float K = ex2f(-__ldg(in + S + C) * LOG2E);
            const size_t A = (S + 3) & ~(size_t)3;
            const int head = (int)(A - S);
            const float4* fp4 = (const float4*)(in + A);
            const int body = (int)((size_t)(S + C) - A);
            const int n4 = body >> 2;
            const int tail = body & 3;
            const int nfull = n4 >> 5;

            float se = 0.0f, sl = 0.0f;
            if (lane < head) acc1(__ldg(in + S + lane), K, se, sl);
            #pragma unroll 4
            for (int k = 0; k < nfull; k++)
                acc4(__ldg(fp4 + (k << 5) + lane), K, se, sl);
            const int i = (nfull << 5) + lane;
            if (i < n4) acc4(__ldg(fp4 + i), K, se, sl);
            if (lane < tail) acc1(__ldg(in + S + C - tail + lane), K, se, sl);

            se = warp_sum(se);
            sl = warp_sum(sl);
            rowacc += __fdividef(sl, se);
        }
    }

    if (lane == 0) sh_row[wid] = rowacc;
    __syncthreads();

    __shared__ bool is_last;
    if (t == 0) {
        float part = 0.0f;
        #pragma unroll
        for (int i = 0; i < WPC; i++) part += sh_row[i];
        g_partials[blockIdx.x] = part;
        __threadfence();
        is_last = (atomicAdd(&g_done, 1) == (int)gridDim.x - 1);
    }
    __syncthreads();

    if (is_last) {
        const int nP = gridDim.x;
        float s = 0.0f;
        for (int i = t; i < nP; i += BLK) s += g_partials[i];
        s = warp_sum(s);
        __shared__ float sh_fin[BLK / 32];
        if (lane == 0) sh_fin[t >> 5] = s;
        __syncthreads();
        if (t == 0) {
            float tot = 0.0f;
            #pragma unroll
            for (int i = 0; i < BLK / 32; i++) tot += sh_fin[i];
            out[0] = tot * (LN2 / (float)B);
            g_done = 0;   // reset for next graph replay
        }
    }
}

extern "C" void kernel_launch(void* const* d_in, const int* in_sizes, int n_in,
                              void* d_out, int out_size)
{
    const float* input = (const float*)d_in[0];
    const int B = in_sizes[1];             // target has B elements
    const int C = in_sizes[0] / B - 1;     // logits per row (row stride C+1)
    float* out = (float*)d_out;

    loss_kernel<<<GRID_CTAS, BLK>>>(input, C, B, out);
}

// round 14
// speedup vs baseline: 1.2028x; 1.2028x over previous
#include <cuda_runtime.h>
#include <cuda_bf16.h>

#define BLK 256
#define WPC 8
#define CTAS_PER_SM 8
#define GRID_CTAS (148 * CTAS_PER_SM)   /* 1184 */
#define MAX_PARTIALS 8192

#define LOG2E 1.44269504088896340736f
#define LN2   0.69314718055994530942f

__device__ float g_partials[MAX_PARTIALS];
__device__ int   g_done = 0;

__device__ __forceinline__ float ex2f(float x) {
    float r; asm("ex2.approx.ftz.f32 %0, %1;" : "=f"(r) : "f"(x)); return r;
}
__device__ __forceinline__ float lg2f(float x) {
    float r; asm("lg2.approx.ftz.f32 %0, %1;" : "=f"(r) : "f"(x)); return r;
}

__inline__ __device__ float warp_sum(float v) {
    #pragma unroll
    for (int o = 16; o > 0; o >>= 1)
        v += __shfl_xor_sync(0xFFFFFFFFu, v, o);
    return v;
}

// accumulate one float4: e = exp(v) = 2^(v*log2e), l = log2(1 + e*K)
__device__ __forceinline__ void acc4(const float4 q, const float K,
                                     float& se, float& sl)
{
    const float e0 = ex2f(q.x * LOG2E);
    const float e1 = ex2f(q.y * LOG2E);
    const float e2 = ex2f(q.z * LOG2E);
    const float e3 = ex2f(q.w * LOG2E);
    const float l0 = lg2f(fmaf(e0, K, 1.0f));
    const float l1 = lg2f(fmaf(e1, K, 1.0f));
    const float l2 = lg2f(fmaf(e2, K, 1.0f));
    const float l3 = lg2f(fmaf(e3, K, 1.0f));
    se += (e0 + e1) + (e2 + e3);
    sl = fmaf(e0, l0, sl);
    sl = fmaf(e1, l1, sl);
    sl = fmaf(e2, l2, sl);
    sl = fmaf(e3, l3, sl);
}

__device__ __forceinline__ void acc1(const float v, const float K,
                                     float& se, float& sl)
{
    const float e = ex2f(v * LOG2E);
    const float l = lg2f(fmaf(e, K, 1.0f));
    se += e;
    sl = fmaf(e, l, sl);
}

// Persistent kernel, one row per warp.
// Fast path (nfull==7, i.e. C=1000 rows): fully unrolled constant-offset
// loads, 4 preloaded + 3 interleaved; zero loop ALU. Max residency (8 CTAs/SM).
__global__ __launch_bounds__(BLK, CTAS_PER_SM) void loss_kernel(
    const float* __restrict__ in, int C, int B, float* __restrict__ out)
{
    const int t    = threadIdx.x;
    const int lane = t & 31;
    const int wid  = t >> 5;
    const int warp_gid = blockIdx.x * WPC + wid;
    const int nwarps   = gridDim.x * WPC;

    __shared__ float sh_row[WPC];

    float rowacc = 0.0f;

    for (int row = warp_gid; row < B; row += nwarps) {
        const size_t S = (size_t)row * (size_t)(C + 1);
        const float extra = __ldg(in + S + C);
        const float K = ex2f(-extra * LOG2E);             // exp(-extra)

        const size_t A = (S + 3) & ~(size_t)3;            // 16B-aligned start
        const int head = (int)(A - S);                    // 0..3 scalar head elems

        const float4* __restrict__ fp4 = (const float4*)(in + A);
        const int body = (int)((size_t)(S + C) - A);
        const int n4   = body >> 2;
        const int tail = body & 3;
        const int nfull = n4 >> 5;

        float se = 0.0f, sl = 0.0f;

        const bool has_h = lane < head;
        const bool has_t = lane < tail;

        if (__builtin_expect(nfull == 7, 1)) {
            // ---- specialized, fully unrolled: constant offsets only ----
            const int  irem  = 224 + lane;                // 7<<5
            const bool has_r = irem < n4;

            float4 q0 = __ldg(fp4 + lane);
            float4 q1 = __ldg(fp4 +  32 + lane);
            float4 q2 = __ldg(fp4 +  64 + lane);
            float4 q3 = __ldg(fp4 +  96 + lane);
            float4 qr; if (has_r) qr = __ldg(fp4 + irem);
            float vh = 0.0f, vt = 0.0f;
            if (has_h) vh = __ldg(in + S + lane);
            if (has_t) vt = __ldg(in + S + C - tail + lane);

            acc4(q0, K, se, sl);
            const float4 q4 = __ldg(fp4 + 128 + lane);
            acc4(q1, K, se, sl);
            const float4 q5 = __ldg(fp4 + 160 + lane);
            acc4(q2, K, se, sl);
            const float4 q6 = __ldg(fp4 + 192 + lane);
            acc4(q3, K, se, sl);
            acc4(q4, K, se, sl);
            acc4(q5, K, se, sl);
            acc4(q6, K, se, sl);

            if (has_r) acc4(qr, K, se, sl);
            if (has_h) acc1(vh, K, se, sl);
            if (has_t) acc1(vt, K, se, sl);
        } else {
            // ---- generic fallback ----
            if (has_h) acc1(__ldg(in + S + lane), K, se, sl);
            #pragma unroll 4
            for (int k = 0; k < nfull; k++)
                acc4(__ldg(fp4 + (k << 5) + lane), K, se, sl);
            const int i = (nfull << 5) + lane;
            if (i < n4) acc4(__ldg(fp4 + i), K, se, sl);
            if (has_t) acc1(__ldg(in + S + C - tail + lane), K, se, sl);
        }

        se = warp_sum(se);
        sl = warp_sum(sl);
        rowacc += __fdividef(sl, se);
    }

    if (lane == 0) sh_row[wid] = rowacc;
    __syncthreads();

    __shared__ bool is_last;
    if (t == 0) {
        float part = 0.0f;
        #pragma unroll
        for (int i = 0; i < WPC; i++) part += sh_row[i];
        g_partials[blockIdx.x] = part;
        __threadfence();
        is_last = (atomicAdd(&g_done, 1) == (int)gridDim.x - 1);
    }
    __syncthreads();

    if (is_last) {
        const int nP = gridDim.x;
        float s = 0.0f;
        for (int i = t; i < nP; i += BLK) s += g_partials[i];
        s = warp_sum(s);
        __shared__ float sh_fin[BLK / 32];
        if (lane == 0) sh_fin[t >> 5] = s;
        __syncthreads();
        if (t == 0) {
            float tot = 0.0f;
            #pragma unroll
            for (int i = 0; i < BLK / 32; i++) tot += sh_fin[i];
            out[0] = tot * (LN2 / (float)B);
            g_done = 0;   // reset for next graph replay
        }
    }
}

extern "C" void kernel_launch(void* const* d_in, const int* in_sizes, int n_in,
                              void* d_out, int out_size)
{
    const float* input = (const float*)d_in[0];
    const int B = in_sizes[1];             // target has B elements
    const int C = in_sizes[0] / B - 1;     // logits per row (row stride C+1)
    float* out = (float*)d_out;

    loss_kernel<<<GRID_CTAS, BLK>>>(input, C, B, out);
}